// round 9
// baseline (speedup 1.0000x reference)
#include <cuda_runtime.h>
#include <cuda_fp16.h>
#include <math.h>
#include <cstdint>

#define NN   50000
#define EE   800000
#define DINF 146
#define DD   128
#define GG   64
#define LL   4
#define NCLS 10
#define ET   (EE + NN)
#define BNEPS 1e-5f

// ---------------- scratch (__device__ globals; no allocs allowed) -----------
__device__ float d_h[NN * DD];        // node features (running h)
__device__ uint2 d_mh[NN * 32];       // m_scaled = dinv*h@W, fp16 (128 halves/row)
__device__ float d_agg[NN * DD];      // aggregated messages (+bias), fp32
__device__ int   d_counts[NN];        // edge-only in-degree (zeroed in k_prep)
__device__ int   d_offs[NN + 1];
__device__ int   d_cursor[NN];
__device__ float d_dinv[NN];
__device__ int   d_ssrc[ET];
__device__ float d_stats[LL * 2 * DD];  // per-layer [sum(128) | sumsq(128)]
__device__ int   d_gcnt[GG];
__device__ int   d_is64;
__device__ float d_wt[LL * DD * DD];  // transposed layer weights [l][n][k]
__device__ float d_wtp[DD * 160];     // transposed+padded emb weights [n][k<160]

// ---------------- index dtype handling --------------------------------------
__device__ __forceinline__ int ld_idx(const void* p, long long i, int is64) {
    return is64 ? (int)((const long long*)p)[i] : ((const int*)p)[i];
}

// ---------------- prep: dtype detect + weight transposes + zeroing -----------
__global__ void k_prep(const float* __restrict__ W_emb,
                       const float* __restrict__ W_gcn, const void* ei) {
    int idx = blockIdx.x * blockDim.x + threadIdx.x;
    if (idx == 0) {
        const long long* p = (const long long*)ei;
        int is64 = 1;
        for (int i = 0; i < 8; i++) {
            long long v = p[i];
            if (v < 0 || v >= NN) is64 = 0;
        }
        d_is64 = is64;
    }
    if (idx < NN) d_counts[idx] = 0;
    if (idx < GG) d_gcnt[idx] = 0;
    if (idx < LL * 2 * DD) d_stats[idx] = 0.f;
    if (idx < DD * 160) {
        int n = idx / 160, k = idx % 160;
        d_wtp[idx] = (k < DINF) ? W_emb[k * DD + n] : 0.f;
    } else if (idx < DD * 160 + LL * DD * DD) {
        int r2 = idx - DD * 160;
        int l = r2 / (DD * DD), r = r2 % (DD * DD);
        int n = r / DD, k = r % DD;
        d_wt[r2] = W_gcn[l * DD * DD + k * DD + n];
    }
}

// ---------------- hist: edge in-degree + batch histogram ---------------------
__global__ void k_hist(const void* ei, const void* batch) {
    int i = blockIdx.x * blockDim.x + threadIdx.x;
    int is64 = d_is64;
    if (i < EE) {
        atomicAdd(&d_counts[ld_idx(ei, (long long)EE + i, is64)], 1);
    } else if (i < EE + NN) {
        atomicAdd(&d_gcnt[ld_idx(batch, i - EE, is64)], 1);
    }
}

// ---------------- scan: offsets + dinv + cursor zero -------------------------
__global__ void k_scan() {
    __shared__ int s[1024];
    const int T = 1024;
    int t = threadIdx.x;
    const int chunk = (NN + T - 1) / T;
    int beg = t * chunk;
    int end = min(beg + chunk, NN);
    int sum = 0;
    for (int i = beg; i < end; i++) {
        int deg = d_counts[i] + 1;           // + self loop
        sum += deg;
        d_dinv[i] = rsqrtf((float)deg);
        d_cursor[i] = 0;
    }
    s[t] = sum;
    __syncthreads();
    for (int off = 1; off < T; off <<= 1) {
        int v = (t >= off) ? s[t - off] : 0;
        __syncthreads();
        s[t] += v;
        __syncthreads();
    }
    int run = (t == 0) ? 0 : s[t - 1];
    for (int i = beg; i < end; i++) { d_offs[i] = run; run += d_counts[i] + 1; }
    if (t == T - 1) d_offs[NN] = run;
}

__global__ void k_scatter(const void* ei) {
    long long e = (long long)blockIdx.x * blockDim.x + threadIdx.x;
    int is64 = d_is64;
    if (e < EE) {
        int s = ld_idx(ei, e, is64);
        int d = ld_idx(ei, (long long)EE + e, is64);
        int p = d_offs[d] + atomicAdd(&d_cursor[d], 1);
        d_ssrc[p] = s;
    } else if (e < ET) {
        int i = (int)(e - EE);
        int p = d_offs[i] + atomicAdd(&d_cursor[i], 1);
        d_ssrc[p] = i;
    }
}

// ======================= tf32 mma.sync GEMM =================================
// C[M,128] = A[M,K] @ Bt[128,K]^T.  CTA tile 128x128, BK=16, 8 warps,
// double-buffered smem, 4x4-transposed rows for single-LDS.128 fragments.
// A-load kept PURE (R4-proven).  HALF_OUT: epilogue writes dinv[row]*acc as
// fp16 into d_mh (factored gcn norm), else fp32 +bias into Cf.

__device__ __forceinline__ float to_tf32(float x) {
    asm("cvt.rna.tf32.f32 %0, %1;" : "=f"(x) : "f"(x));
    return x;
}

__device__ __forceinline__ void mma_tf32(float* d, uint32_t a0, uint32_t a1,
                                         uint32_t a2, uint32_t a3,
                                         uint32_t b0, uint32_t b1) {
    asm volatile(
        "mma.sync.aligned.m16n8k8.row.col.f32.tf32.tf32.f32 "
        "{%0,%1,%2,%3}, {%4,%5,%6,%7}, {%8,%9}, {%0,%1,%2,%3};"
        : "+f"(d[0]), "+f"(d[1]), "+f"(d[2]), "+f"(d[3])
        : "r"(a0), "r"(a1), "r"(a2), "r"(a3), "r"(b0), "r"(b1));
}

template<bool PADK, bool HALF_OUT>
__global__ __launch_bounds__(256, 2) void k_gemm_mma(
    const float* __restrict__ A, int lda, int kmax, int kiters,
    const float* __restrict__ Bt, int ldb,
    const float* __restrict__ bias, float* __restrict__ Cf, int M)
{
    __shared__ __align__(16) float As[2][128 * 16];
    __shared__ __align__(16) float Bs[2][128 * 16];

    int t = threadIdx.x;
    int wid = t >> 5, lane = t & 31;
    int wm = wid & 3, wn = wid >> 2;
    int qr = lane >> 2, qc = lane & 3;
    int m0 = blockIdx.x * 128;

    float acc[2][8][4];
#pragma unroll
    for (int mi = 0; mi < 2; mi++)
#pragma unroll
        for (int ni = 0; ni < 8; ni++)
#pragma unroll
            for (int j = 0; j < 4; j++) acc[mi][ni][j] = 0.f;

    float ra[2][4], rb[2][4];

    auto load_tile = [&](int kk) {
#pragma unroll
        for (int i = 0; i < 2; i++) {
            int slot = t + i * 256;
            int r = slot >> 2, c = slot & 3;
            int grow = m0 + r;
            if (PADK) {
#pragma unroll
                for (int d = 0; d < 4; d++) {
                    int k = kk + c * 4 + d;
                    ra[i][d] = (grow < M && k < kmax)
                             ? A[(size_t)grow * lda + k] : 0.f;
                }
            } else {
                float4 v = make_float4(0.f, 0.f, 0.f, 0.f);
                if (grow < M)
                    v = *reinterpret_cast<const float4*>(
                        A + (size_t)grow * lda + kk + c * 4);
                ra[i][0] = v.x; ra[i][1] = v.y; ra[i][2] = v.z; ra[i][3] = v.w;
            }
            float4 w = *reinterpret_cast<const float4*>(
                Bt + (size_t)r * ldb + kk + c * 4);
            rb[i][0] = w.x; rb[i][1] = w.y; rb[i][2] = w.z; rb[i][3] = w.w;
        }
    };

    load_tile(0);

    int buf = 0;
    for (int it = 0; it < kiters; it++) {
#pragma unroll
        for (int i = 0; i < 2; i++) {
            int slot = t + i * 256;
            int r = slot >> 2, c = slot & 3;
#pragma unroll
            for (int d = 0; d < 4; d++) {
                As[buf][r * 16 + d * 4 + c] = to_tf32(ra[i][d]);
                Bs[buf][r * 16 + d * 4 + c] = to_tf32(rb[i][d]);
            }
        }
        __syncthreads();

        if (it + 1 < kiters) load_tile((it + 1) * 16);

        const uint4* As4 = reinterpret_cast<const uint4*>(As[buf]);
        const uint4* Bs4 = reinterpret_cast<const uint4*>(Bs[buf]);

        uint4 af[2][2];
#pragma unroll
        for (int mi = 0; mi < 2; mi++)
#pragma unroll
            for (int h = 0; h < 2; h++) {
                int row = wm * 32 + mi * 16 + h * 8 + qr;
                af[mi][h] = As4[row * 4 + qc];
            }
#pragma unroll
        for (int ni = 0; ni < 8; ni++) {
            int row = wn * 64 + ni * 8 + qr;
            uint4 bf = Bs4[row * 4 + qc];
#pragma unroll
            for (int mi = 0; mi < 2; mi++) {
                mma_tf32(acc[mi][ni], af[mi][0].x, af[mi][1].x,
                         af[mi][0].y, af[mi][1].y, bf.x, bf.y);
                mma_tf32(acc[mi][ni], af[mi][0].z, af[mi][1].z,
                         af[mi][0].w, af[mi][1].w, bf.z, bf.w);
            }
        }
        __syncthreads();
        buf ^= 1;
    }

    // ---- epilogue ----
#pragma unroll
    for (int mi = 0; mi < 2; mi++) {
        int r0 = m0 + wm * 32 + mi * 16 + qr;
        int r1 = r0 + 8;
        if (HALF_OUT) {
            float dv0 = (r0 < M) ? d_dinv[r0] : 0.f;
            float dv1 = (r1 < M) ? d_dinv[r1] : 0.f;
            __half2* mh2 = reinterpret_cast<__half2*>(d_mh);
#pragma unroll
            for (int ni = 0; ni < 8; ni++) {
                int col = wn * 64 + ni * 8 + qc * 2;
                if (r0 < M)
                    mh2[(size_t)r0 * 64 + (col >> 1)] =
                        __floats2half2_rn(acc[mi][ni][0] * dv0, acc[mi][ni][1] * dv0);
                if (r1 < M)
                    mh2[(size_t)r1 * 64 + (col >> 1)] =
                        __floats2half2_rn(acc[mi][ni][2] * dv1, acc[mi][ni][3] * dv1);
            }
        } else {
#pragma unroll
            for (int ni = 0; ni < 8; ni++) {
                int col = wn * 64 + ni * 8 + qc * 2;
                float b0 = 0.f, b1 = 0.f;
                if (bias) { b0 = bias[col]; b1 = bias[col + 1]; }
                if (r0 < M) {
                    float2 o = make_float2(acc[mi][ni][0] + b0, acc[mi][ni][1] + b1);
                    *reinterpret_cast<float2*>(Cf + (size_t)r0 * DD + col) = o;
                }
                if (r1 < M) {
                    float2 o = make_float2(acc[mi][ni][2] + b0, acc[mi][ni][3] + b1);
                    *reinterpret_cast<float2*>(Cf + (size_t)r1 * DD + col) = o;
                }
            }
        }
    }
}

// ---------------- edge aggregation + BN stats --------------------------------
// warp per node: agg[n] = dinv[n] * sum_e m_scaled[src[e]] + bias; stats fused.
__global__ __launch_bounds__(256) void k_agg_stats(
    const float* __restrict__ bias, float* __restrict__ stats)
{
    __shared__ float ssum[DD], ssq[DD];
    int t = threadIdx.x;
    if (t < DD) { ssum[t] = 0.f; ssq[t] = 0.f; }
    __syncthreads();

    int node = (blockIdx.x * 256 + t) >> 5;
    int lane = t & 31;
    if (node < NN) {
        int e0 = d_offs[node], e1 = d_offs[node + 1];
        float a0 = 0.f, a1 = 0.f, a2 = 0.f, a3 = 0.f;
        int e = e0;
        for (; e + 2 <= e1; e += 2) {
            int s0 = d_ssrc[e], s1 = d_ssrc[e + 1];
            uint2 v0 = d_mh[(size_t)s0 * 32 + lane];
            uint2 v1 = d_mh[(size_t)s1 * 32 + lane];
            float2 f00 = __half22float2(*reinterpret_cast<__half2*>(&v0.x));
            float2 f01 = __half22float2(*reinterpret_cast<__half2*>(&v0.y));
            float2 f10 = __half22float2(*reinterpret_cast<__half2*>(&v1.x));
            float2 f11 = __half22float2(*reinterpret_cast<__half2*>(&v1.y));
            a0 += f00.x + f10.x; a1 += f00.y + f10.y;
            a2 += f01.x + f11.x; a3 += f01.y + f11.y;
        }
        if (e < e1) {
            int s0 = d_ssrc[e];
            uint2 v0 = d_mh[(size_t)s0 * 32 + lane];
            float2 f00 = __half22float2(*reinterpret_cast<__half2*>(&v0.x));
            float2 f01 = __half22float2(*reinterpret_cast<__half2*>(&v0.y));
            a0 += f00.x; a1 += f00.y; a2 += f01.x; a3 += f01.y;
        }
        float dv = d_dinv[node];
        float4 b = reinterpret_cast<const float4*>(bias)[lane];
        a0 = a0 * dv + b.x;
        a1 = a1 * dv + b.y;
        a2 = a2 * dv + b.z;
        a3 = a3 * dv + b.w;
        reinterpret_cast<float4*>(d_agg)[(size_t)node * 32 + lane] =
            make_float4(a0, a1, a2, a3);
        int c = lane * 4;
        atomicAdd(&ssum[c + 0], a0); atomicAdd(&ssq[c + 0], a0 * a0);
        atomicAdd(&ssum[c + 1], a1); atomicAdd(&ssq[c + 1], a1 * a1);
        atomicAdd(&ssum[c + 2], a2); atomicAdd(&ssq[c + 2], a2 * a2);
        atomicAdd(&ssum[c + 3], a3); atomicAdd(&ssq[c + 3], a3 * a3);
    }
    __syncthreads();
    if (t < DD) {
        atomicAdd(&stats[t], ssum[t]);
        atomicAdd(&stats[DD + t], ssq[t]);
    }
}

// ---------------- BN apply: h += relu(agg*sc+sh)  (streaming, float4) --------
__global__ __launch_bounds__(256) void k_bn_apply(
    const float* __restrict__ stats,
    const float* __restrict__ gamma, const float* __restrict__ beta)
{
    __shared__ float s_sc[DD], s_sh[DD];
    int t = threadIdx.x;
    if (t < DD) {
        float mu = stats[t] * (1.f / NN);
        float var = stats[DD + t] * (1.f / NN) - mu * mu;
        float sc = gamma[t] * rsqrtf(var + BNEPS);
        s_sc[t] = sc;
        s_sh[t] = beta[t] - mu * sc;
    }
    __syncthreads();

    const long long total = (long long)NN * 32;   // float4 elements
    for (long long i = (long long)blockIdx.x * 256 + t; i < total;
         i += (long long)gridDim.x * 256) {
        int c4 = (int)(i & 31) * 4;
        float4 a = reinterpret_cast<const float4*>(d_agg)[i];
        float4 h = reinterpret_cast<const float4*>(d_h)[i];
        h.x += fmaxf(0.f, a.x * s_sc[c4 + 0] + s_sh[c4 + 0]);
        h.y += fmaxf(0.f, a.y * s_sc[c4 + 1] + s_sh[c4 + 1]);
        h.z += fmaxf(0.f, a.z * s_sc[c4 + 2] + s_sh[c4 + 2]);
        h.w += fmaxf(0.f, a.w * s_sc[c4 + 3] + s_sh[c4 + 3]);
        reinterpret_cast<float4*>(d_h)[i] = h;
    }
}

// ---------------- fused BN3 + mean-pool + MLP readout -------------------------
__global__ __launch_bounds__(256) void k_pool_mlp(
    const float* __restrict__ gamma, const float* __restrict__ beta,
    const float* __restrict__ W1, const float* __restrict__ b1,
    const float* __restrict__ W2, const float* __restrict__ b2,
    const float* __restrict__ W3, const float* __restrict__ b3,
    float* __restrict__ out)
{
    __shared__ float sc[DD], sh[DD], hg[DD], z1[64], z2[32], part[2][DD];
    __shared__ int sst;
    int g = blockIdx.x, t = threadIdx.x;
    int tt = t & 127, half = t >> 7;

    if (t < DD) {
        const float* st = d_stats + 3 * 2 * DD;
        float mu = st[t] * (1.f / NN);
        float var = st[DD + t] * (1.f / NN) - mu * mu;
        float s = gamma[t] * rsqrtf(var + BNEPS);
        sc[t] = s;
        sh[t] = beta[t] - mu * s;
    }
    if (t == 0) {
        int run = 0;
        for (int i = 0; i < g; i++) run += d_gcnt[i];
        sst = run;
    }
    __syncthreads();

    int s0 = sst, c = d_gcnt[g];
    float acc = 0.f;
    for (int r = half; r < c; r += 2) {
        size_t off = (size_t)(s0 + r) * DD + tt;
        acc += d_h[off] + fmaxf(0.f, d_agg[off] * sc[tt] + sh[tt]);
    }
    part[half][tt] = acc;
    __syncthreads();
    if (t < DD) hg[t] = (part[0][t] + part[1][t]) / fmaxf((float)c, 1.f);
    __syncthreads();

    if (t < 64) {
        float a = b1[t];
        for (int k = 0; k < DD; k++) a = fmaf(hg[k], W1[k * 64 + t], a);
        z1[t] = fmaxf(0.f, a);
    }
    __syncthreads();
    if (t < 32) {
        float a = b2[t];
        for (int k = 0; k < 64; k++) a = fmaf(z1[k], W2[k * 32 + t], a);
        z2[t] = fmaxf(0.f, a);
    }
    __syncthreads();
    if (t < NCLS) {
        float a = b3[t];
        for (int k = 0; k < 32; k++) a = fmaf(z2[k], W3[k * NCLS + t], a);
        out[g * NCLS + t] = a;
    }
}

// ---------------- launch ------------------------------------------------------
extern "C" void kernel_launch(void* const* d_in, const int* in_sizes, int n_in,
                              void* d_out, int out_size) {
    const float* x        = (const float*)d_in[0];
    const void*  ei       = d_in[1];
    const void*  batch    = d_in[2];
    const float* W_emb    = (const float*)d_in[3];
    const float* b_emb    = (const float*)d_in[4];
    const float* W_gcn    = (const float*)d_in[5];
    const float* b_gcn    = (const float*)d_in[6];
    const float* bn_gamma = (const float*)d_in[7];
    const float* bn_beta  = (const float*)d_in[8];
    const float* W_r1     = (const float*)d_in[9];
    const float* b_r1     = (const float*)d_in[10];
    const float* W_r2     = (const float*)d_in[11];
    const float* b_r2     = (const float*)d_in[12];
    const float* W_r3     = (const float*)d_in[13];
    const float* b_r3     = (const float*)d_in[14];
    float* out = (float*)d_out;

    float* p_h;      cudaGetSymbolAddress((void**)&p_h, d_h);
    float* p_wt;     cudaGetSymbolAddress((void**)&p_wt, d_wt);
    float* p_wtp;    cudaGetSymbolAddress((void**)&p_wtp, d_wtp);
    float* p_stats;  cudaGetSymbolAddress((void**)&p_stats, d_stats);

    const int NBLK = (NN + 127) / 128;   // 391
    const int PREP = DD * 160 + LL * DD * DD;

    // --- preprocessing (also zeroes counts / gcnt / stats) ---
    k_prep<<<(PREP + 255) / 256, 256>>>(W_emb, W_gcn, ei);
    k_hist<<<(EE + NN + 255) / 256, 256>>>(ei, batch);
    k_scan<<<1, 1024>>>();
    k_scatter<<<(ET + 255) / 256, 256>>>(ei);

    // --- embedding: h0 = x @ W_emb + b_emb ---
    k_gemm_mma<true, false><<<NBLK, 256>>>(
        x, DINF, DINF, 10, p_wtp, 160, b_emb, p_h, NN);

    // --- GCN layers: GEMM -> agg+stats -> bn_apply (last layer's BN in pool) ---
    for (int l = 0; l < LL; l++) {
        k_gemm_mma<false, true><<<NBLK, 256>>>(
            p_h, DD, DD, 8, p_wt + l * DD * DD, DD, nullptr, nullptr, NN);
        k_agg_stats<<<NN / 8, 256>>>(b_gcn + l * DD, p_stats + l * 2 * DD);
        if (l < LL - 1)
            k_bn_apply<<<592, 256>>>(p_stats + l * 2 * DD,
                                     bn_gamma + l * DD, bn_beta + l * DD);
    }

    // --- fused BN3 + mean-pool + MLP ---
    k_pool_mlp<<<GG, 256>>>(bn_gamma + 3 * DD, bn_beta + 3 * DD,
                            W_r1, b_r1, W_r2, b_r2, W_r3, b_r3, out);
}

// round 10
// speedup vs baseline: 1.3336x; 1.3336x over previous
#include <cuda_runtime.h>
#include <cuda_fp16.h>
#include <math.h>
#include <cstdint>

#define NN   50000
#define EE   800000
#define DINF 146
#define DD   128
#define GG   64
#define LL   4
#define NCLS 10
#define ET   (EE + NN)
#define BNEPS 1e-5f

// ---------------- scratch (__device__ globals; no allocs allowed) -----------
__device__ float d_h[NN * DD];        // node features (running h)
__device__ uint2 d_mh[NN * 32];       // m_scaled = dinv*h@W, fp16 (128 halves/row)
__device__ float d_agg[NN * DD];      // aggregated messages (+bias), fp32
__device__ int   d_counts[NN];        // edge-only in-degree (zeroed in k_prep)
__device__ int   d_offs[NN + 1];
__device__ int   d_cursor[NN];
__device__ float d_dinv[NN];
__device__ int   d_ssrc[ET];
__device__ float d_stats[LL * 2 * DD];  // per-layer [sum(128) | sumsq(128)], zeroed in k_prep
__device__ int   d_gcnt[GG];
__device__ int   d_is64;
__device__ float d_wt[LL * DD * DD];  // transposed layer weights [l][n][k]
__device__ float d_wtp[DD * 160];     // transposed+padded emb weights [n][k<160]

// ---------------- index dtype handling --------------------------------------
__device__ __forceinline__ int ld_idx(const void* p, long long i, int is64) {
    return is64 ? (int)((const long long*)p)[i] : ((const int*)p)[i];
}

// ---------------- prep: dtype detect + weight transposes + zeroing -----------
__global__ void k_prep(const float* __restrict__ W_emb,
                       const float* __restrict__ W_gcn, const void* ei) {
    int idx = blockIdx.x * blockDim.x + threadIdx.x;
    if (idx == 0) {
        const long long* p = (const long long*)ei;
        int is64 = 1;
        for (int i = 0; i < 8; i++) {
            long long v = p[i];
            if (v < 0 || v >= NN) is64 = 0;
        }
        d_is64 = is64;
    }
    if (idx < NN) d_counts[idx] = 0;
    if (idx < GG) d_gcnt[idx] = 0;
    if (idx < LL * 2 * DD) d_stats[idx] = 0.f;
    if (idx < DD * 160) {
        int n = idx / 160, k = idx % 160;
        d_wtp[idx] = (k < DINF) ? W_emb[k * DD + n] : 0.f;
    } else if (idx < DD * 160 + LL * DD * DD) {
        int r2 = idx - DD * 160;
        int l = r2 / (DD * DD), r = r2 % (DD * DD);
        int n = r / DD, k = r % DD;
        d_wt[r2] = W_gcn[l * DD * DD + k * DD + n];
    }
}

// ---------------- hist: edge in-degree + batch histogram ---------------------
__global__ void k_hist(const void* ei, const void* batch) {
    int i = blockIdx.x * blockDim.x + threadIdx.x;
    int is64 = d_is64;
    if (i < EE) {
        atomicAdd(&d_counts[ld_idx(ei, (long long)EE + i, is64)], 1);
    } else if (i < EE + NN) {
        atomicAdd(&d_gcnt[ld_idx(batch, i - EE, is64)], 1);
    }
}

// ---------------- scan: offsets + dinv + cursor zero -------------------------
__global__ void k_scan() {
    __shared__ int s[1024];
    const int T = 1024;
    int t = threadIdx.x;
    const int chunk = (NN + T - 1) / T;
    int beg = t * chunk;
    int end = min(beg + chunk, NN);
    int sum = 0;
    for (int i = beg; i < end; i++) {
        int deg = d_counts[i] + 1;           // + self loop
        sum += deg;
        d_dinv[i] = rsqrtf((float)deg);
        d_cursor[i] = 0;
    }
    s[t] = sum;
    __syncthreads();
    for (int off = 1; off < T; off <<= 1) {
        int v = (t >= off) ? s[t - off] : 0;
        __syncthreads();
        s[t] += v;
        __syncthreads();
    }
    int run = (t == 0) ? 0 : s[t - 1];
    for (int i = beg; i < end; i++) { d_offs[i] = run; run += d_counts[i] + 1; }
    if (t == T - 1) d_offs[NN] = run;
}

__global__ void k_scatter(const void* ei) {
    long long e = (long long)blockIdx.x * blockDim.x + threadIdx.x;
    int is64 = d_is64;
    if (e < EE) {
        int s = ld_idx(ei, e, is64);
        int d = ld_idx(ei, (long long)EE + e, is64);
        int p = d_offs[d] + atomicAdd(&d_cursor[d], 1);
        d_ssrc[p] = s;
    } else if (e < ET) {
        int i = (int)(e - EE);
        int p = d_offs[i] + atomicAdd(&d_cursor[i], 1);
        d_ssrc[p] = i;
    }
}

// ======================= tf32 mma.sync GEMM =================================
// C[M,128] = A[M,K] @ Bt[128,K]^T.  CTA tile 128x128, BK=16, 8 warps,
// double-buffered smem, 4x4-transposed rows for single-LDS.128 fragments.
// FUSE_BN: A-load applies h_new = h + relu(agg*scale+shift), writes h back.
// HALF_OUT: epilogue writes dinv[row]*acc as fp16 into d_mh.

__device__ __forceinline__ float to_tf32(float x) {
    asm("cvt.rna.tf32.f32 %0, %1;" : "=f"(x) : "f"(x));
    return x;
}

__device__ __forceinline__ void mma_tf32(float* d, uint32_t a0, uint32_t a1,
                                         uint32_t a2, uint32_t a3,
                                         uint32_t b0, uint32_t b1) {
    asm volatile(
        "mma.sync.aligned.m16n8k8.row.col.f32.tf32.tf32.f32 "
        "{%0,%1,%2,%3}, {%4,%5,%6,%7}, {%8,%9}, {%0,%1,%2,%3};"
        : "+f"(d[0]), "+f"(d[1]), "+f"(d[2]), "+f"(d[3])
        : "r"(a0), "r"(a1), "r"(a2), "r"(a3), "r"(b0), "r"(b1));
}

template<bool PADK, bool FUSE_BN, bool HALF_OUT>
__global__ __launch_bounds__(256, 2) void k_gemm_mma(
    const float* __restrict__ A, float* __restrict__ Aw,
    int lda, int kmax, int kiters,
    const float* __restrict__ Bt, int ldb,
    const float* __restrict__ bias, float* __restrict__ Cf,
    const float* __restrict__ statsPrev,
    const float* __restrict__ gammaPrev, const float* __restrict__ betaPrev,
    const float* __restrict__ aggPrev, int M)
{
    __shared__ __align__(16) float As[2][128 * 16];
    __shared__ __align__(16) float Bs[2][128 * 16];
    __shared__ float s_sc[DD], s_sh[DD];

    int t = threadIdx.x;
    int wid = t >> 5, lane = t & 31;
    int wm = wid & 3, wn = wid >> 2;
    int qr = lane >> 2, qc = lane & 3;
    int m0 = blockIdx.x * 128;

    if (FUSE_BN) {
        if (t < DD) {
            float mu = statsPrev[t] * (1.f / NN);
            float var = statsPrev[DD + t] * (1.f / NN) - mu * mu;
            float sc = gammaPrev[t] * rsqrtf(var + BNEPS);
            s_sc[t] = sc;
            s_sh[t] = betaPrev[t] - mu * sc;
        }
        __syncthreads();
    }

    float acc[2][8][4];
#pragma unroll
    for (int mi = 0; mi < 2; mi++)
#pragma unroll
        for (int ni = 0; ni < 8; ni++)
#pragma unroll
            for (int j = 0; j < 4; j++) acc[mi][ni][j] = 0.f;

    float ra[2][4], rb[2][4];

    auto load_tile = [&](int kk) {
#pragma unroll
        for (int i = 0; i < 2; i++) {
            int slot = t + i * 256;
            int r = slot >> 2, c = slot & 3;
            int grow = m0 + r;
            if (PADK) {
#pragma unroll
                for (int d = 0; d < 4; d++) {
                    int k = kk + c * 4 + d;
                    ra[i][d] = (grow < M && k < kmax)
                             ? A[(size_t)grow * lda + k] : 0.f;
                }
            } else {
                float4 v = make_float4(0.f, 0.f, 0.f, 0.f);
                if (grow < M) {
                    size_t off = (size_t)grow * lda + kk + c * 4;
                    v = *reinterpret_cast<const float4*>(A + off);
                    if (FUSE_BN) {
                        float4 g = *reinterpret_cast<const float4*>(aggPrev + off);
                        int col = kk + c * 4;
                        v.x += fmaxf(0.f, g.x * s_sc[col + 0] + s_sh[col + 0]);
                        v.y += fmaxf(0.f, g.y * s_sc[col + 1] + s_sh[col + 1]);
                        v.z += fmaxf(0.f, g.z * s_sc[col + 2] + s_sh[col + 2]);
                        v.w += fmaxf(0.f, g.w * s_sc[col + 3] + s_sh[col + 3]);
                        *reinterpret_cast<float4*>(Aw + off) = v;
                    }
                }
                ra[i][0] = v.x; ra[i][1] = v.y; ra[i][2] = v.z; ra[i][3] = v.w;
            }
            float4 w = *reinterpret_cast<const float4*>(
                Bt + (size_t)r * ldb + kk + c * 4);
            rb[i][0] = w.x; rb[i][1] = w.y; rb[i][2] = w.z; rb[i][3] = w.w;
        }
    };

    load_tile(0);

    int buf = 0;
    for (int it = 0; it < kiters; it++) {
#pragma unroll
        for (int i = 0; i < 2; i++) {
            int slot = t + i * 256;
            int r = slot >> 2, c = slot & 3;
#pragma unroll
            for (int d = 0; d < 4; d++) {
                As[buf][r * 16 + d * 4 + c] = to_tf32(ra[i][d]);
                Bs[buf][r * 16 + d * 4 + c] = to_tf32(rb[i][d]);
            }
        }
        __syncthreads();

        if (it + 1 < kiters) load_tile((it + 1) * 16);

        const uint4* As4 = reinterpret_cast<const uint4*>(As[buf]);
        const uint4* Bs4 = reinterpret_cast<const uint4*>(Bs[buf]);

        uint4 af[2][2];
#pragma unroll
        for (int mi = 0; mi < 2; mi++)
#pragma unroll
            for (int h = 0; h < 2; h++) {
                int row = wm * 32 + mi * 16 + h * 8 + qr;
                af[mi][h] = As4[row * 4 + qc];
            }
#pragma unroll
        for (int ni = 0; ni < 8; ni++) {
            int row = wn * 64 + ni * 8 + qr;
            uint4 bf = Bs4[row * 4 + qc];
#pragma unroll
            for (int mi = 0; mi < 2; mi++) {
                mma_tf32(acc[mi][ni], af[mi][0].x, af[mi][1].x,
                         af[mi][0].y, af[mi][1].y, bf.x, bf.y);
                mma_tf32(acc[mi][ni], af[mi][0].z, af[mi][1].z,
                         af[mi][0].w, af[mi][1].w, bf.z, bf.w);
            }
        }
        __syncthreads();
        buf ^= 1;
    }

    // ---- epilogue ----
#pragma unroll
    for (int mi = 0; mi < 2; mi++) {
        int r0 = m0 + wm * 32 + mi * 16 + qr;
        int r1 = r0 + 8;
        if (HALF_OUT) {
            float dv0 = (r0 < M) ? d_dinv[r0] : 0.f;
            float dv1 = (r1 < M) ? d_dinv[r1] : 0.f;
            __half2* mh2 = reinterpret_cast<__half2*>(d_mh);
#pragma unroll
            for (int ni = 0; ni < 8; ni++) {
                int col = wn * 64 + ni * 8 + qc * 2;
                if (r0 < M)
                    mh2[(size_t)r0 * 64 + (col >> 1)] =
                        __floats2half2_rn(acc[mi][ni][0] * dv0, acc[mi][ni][1] * dv0);
                if (r1 < M)
                    mh2[(size_t)r1 * 64 + (col >> 1)] =
                        __floats2half2_rn(acc[mi][ni][2] * dv1, acc[mi][ni][3] * dv1);
            }
        } else {
#pragma unroll
            for (int ni = 0; ni < 8; ni++) {
                int col = wn * 64 + ni * 8 + qc * 2;
                float b0 = 0.f, b1 = 0.f;
                if (bias) { b0 = bias[col]; b1 = bias[col + 1]; }
                if (r0 < M) {
                    float2 o = make_float2(acc[mi][ni][0] + b0, acc[mi][ni][1] + b1);
                    *reinterpret_cast<float2*>(Cf + (size_t)r0 * DD + col) = o;
                }
                if (r1 < M) {
                    float2 o = make_float2(acc[mi][ni][2] + b0, acc[mi][ni][3] + b1);
                    *reinterpret_cast<float2*>(Cf + (size_t)r1 * DD + col) = o;
                }
            }
        }
    }
}

// ---------------- edge aggregation + BN stats --------------------------------
// warp per node: agg[n] = dinv[n] * sum_e m_scaled[src[e]] + bias; stats fused.
__global__ __launch_bounds__(256) void k_agg_stats(
    const float* __restrict__ bias, float* __restrict__ stats)
{
    __shared__ float ssum[DD], ssq[DD];
    int t = threadIdx.x;
    if (t < DD) { ssum[t] = 0.f; ssq[t] = 0.f; }
    __syncthreads();

    int node = (blockIdx.x * 256 + t) >> 5;
    int lane = t & 31;
    if (node < NN) {
        int e0 = d_offs[node], e1 = d_offs[node + 1];
        float a0 = 0.f, a1 = 0.f, a2 = 0.f, a3 = 0.f;
        int e = e0;
        for (; e + 4 <= e1; e += 4) {
            int s0 = d_ssrc[e],     s1 = d_ssrc[e + 1];
            int s2 = d_ssrc[e + 2], s3 = d_ssrc[e + 3];
            uint2 v0 = d_mh[(size_t)s0 * 32 + lane];
            uint2 v1 = d_mh[(size_t)s1 * 32 + lane];
            uint2 v2 = d_mh[(size_t)s2 * 32 + lane];
            uint2 v3 = d_mh[(size_t)s3 * 32 + lane];
            float2 f00 = __half22float2(*reinterpret_cast<__half2*>(&v0.x));
            float2 f01 = __half22float2(*reinterpret_cast<__half2*>(&v0.y));
            float2 f10 = __half22float2(*reinterpret_cast<__half2*>(&v1.x));
            float2 f11 = __half22float2(*reinterpret_cast<__half2*>(&v1.y));
            float2 f20 = __half22float2(*reinterpret_cast<__half2*>(&v2.x));
            float2 f21 = __half22float2(*reinterpret_cast<__half2*>(&v2.y));
            float2 f30 = __half22float2(*reinterpret_cast<__half2*>(&v3.x));
            float2 f31 = __half22float2(*reinterpret_cast<__half2*>(&v3.y));
            a0 += (f00.x + f10.x) + (f20.x + f30.x);
            a1 += (f00.y + f10.y) + (f20.y + f30.y);
            a2 += (f01.x + f11.x) + (f21.x + f31.x);
            a3 += (f01.y + f11.y) + (f21.y + f31.y);
        }
        for (; e < e1; e++) {
            int s0 = d_ssrc[e];
            uint2 v0 = d_mh[(size_t)s0 * 32 + lane];
            float2 f00 = __half22float2(*reinterpret_cast<__half2*>(&v0.x));
            float2 f01 = __half22float2(*reinterpret_cast<__half2*>(&v0.y));
            a0 += f00.x; a1 += f00.y; a2 += f01.x; a3 += f01.y;
        }
        float dv = d_dinv[node];
        float4 b = reinterpret_cast<const float4*>(bias)[lane];
        a0 = a0 * dv + b.x;
        a1 = a1 * dv + b.y;
        a2 = a2 * dv + b.z;
        a3 = a3 * dv + b.w;
        reinterpret_cast<float4*>(d_agg)[(size_t)node * 32 + lane] =
            make_float4(a0, a1, a2, a3);
        int c = lane * 4;
        atomicAdd(&ssum[c + 0], a0); atomicAdd(&ssq[c + 0], a0 * a0);
        atomicAdd(&ssum[c + 1], a1); atomicAdd(&ssq[c + 1], a1 * a1);
        atomicAdd(&ssum[c + 2], a2); atomicAdd(&ssq[c + 2], a2 * a2);
        atomicAdd(&ssum[c + 3], a3); atomicAdd(&ssq[c + 3], a3 * a3);
    }
    __syncthreads();
    if (t < DD) {
        atomicAdd(&stats[t], ssum[t]);
        atomicAdd(&stats[DD + t], ssq[t]);
    }
}

// ---------------- fused BN3 + mean-pool + MLP readout -------------------------
__global__ __launch_bounds__(256) void k_pool_mlp(
    const float* __restrict__ gamma, const float* __restrict__ beta,
    const float* __restrict__ W1, const float* __restrict__ b1,
    const float* __restrict__ W2, const float* __restrict__ b2,
    const float* __restrict__ W3, const float* __restrict__ b3,
    float* __restrict__ out)
{
    __shared__ float sc[DD], sh[DD], hg[DD], z1[64], z2[32], part[2][DD];
    __shared__ int sst;
    int g = blockIdx.x, t = threadIdx.x;
    int tt = t & 127, half = t >> 7;

    if (t < DD) {
        const float* st = d_stats + 3 * 2 * DD;
        float mu = st[t] * (1.f / NN);
        float var = st[DD + t] * (1.f / NN) - mu * mu;
        float s = gamma[t] * rsqrtf(var + BNEPS);
        sc[t] = s;
        sh[t] = beta[t] - mu * s;
    }
    if (t == 0) {
        int run = 0;
        for (int i = 0; i < g; i++) run += d_gcnt[i];
        sst = run;
    }
    __syncthreads();

    int s0 = sst, c = d_gcnt[g];
    float acc = 0.f;
    for (int r = half; r < c; r += 2) {
        size_t off = (size_t)(s0 + r) * DD + tt;
        acc += d_h[off] + fmaxf(0.f, d_agg[off] * sc[tt] + sh[tt]);
    }
    part[half][tt] = acc;
    __syncthreads();
    if (t < DD) hg[t] = (part[0][t] + part[1][t]) / fmaxf((float)c, 1.f);
    __syncthreads();

    if (t < 64) {
        float a = b1[t];
        for (int k = 0; k < DD; k++) a = fmaf(hg[k], W1[k * 64 + t], a);
        z1[t] = fmaxf(0.f, a);
    }
    __syncthreads();
    if (t < 32) {
        float a = b2[t];
        for (int k = 0; k < 64; k++) a = fmaf(z1[k], W2[k * 32 + t], a);
        z2[t] = fmaxf(0.f, a);
    }
    __syncthreads();
    if (t < NCLS) {
        float a = b3[t];
        for (int k = 0; k < 32; k++) a = fmaf(z2[k], W3[k * NCLS + t], a);
        out[g * NCLS + t] = a;
    }
}

// ---------------- launch ------------------------------------------------------
extern "C" void kernel_launch(void* const* d_in, const int* in_sizes, int n_in,
                              void* d_out, int out_size) {
    const float* x        = (const float*)d_in[0];
    const void*  ei       = d_in[1];
    const void*  batch    = d_in[2];
    const float* W_emb    = (const float*)d_in[3];
    const float* b_emb    = (const float*)d_in[4];
    const float* W_gcn    = (const float*)d_in[5];
    const float* b_gcn    = (const float*)d_in[6];
    const float* bn_gamma = (const float*)d_in[7];
    const float* bn_beta  = (const float*)d_in[8];
    const float* W_r1     = (const float*)d_in[9];
    const float* b_r1     = (const float*)d_in[10];
    const float* W_r2     = (const float*)d_in[11];
    const float* b_r2     = (const float*)d_in[12];
    const float* W_r3     = (const float*)d_in[13];
    const float* b_r3     = (const float*)d_in[14];
    float* out = (float*)d_out;

    float* p_h;      cudaGetSymbolAddress((void**)&p_h, d_h);
    float* p_agg;    cudaGetSymbolAddress((void**)&p_agg, d_agg);
    float* p_wt;     cudaGetSymbolAddress((void**)&p_wt, d_wt);
    float* p_wtp;    cudaGetSymbolAddress((void**)&p_wtp, d_wtp);
    float* p_stats;  cudaGetSymbolAddress((void**)&p_stats, d_stats);

    const int NBLK = (NN + 127) / 128;   // 391
    const int PREP = DD * 160 + LL * DD * DD;

    // --- preprocessing (also zeroes counts / gcnt / stats) ---
    k_prep<<<(PREP + 255) / 256, 256>>>(W_emb, W_gcn, ei);
    k_hist<<<(EE + NN + 255) / 256, 256>>>(ei, batch);
    k_scan<<<1, 1024>>>();
    k_scatter<<<(ET + 255) / 256, 256>>>(ei);

    // --- embedding: h0 = x @ W_emb + b_emb ---
    k_gemm_mma<true, false, false><<<NBLK, 256>>>(
        x, nullptr, DINF, DINF, 10, p_wtp, 160, b_emb, p_h,
        nullptr, nullptr, nullptr, nullptr, NN);

    // --- layer 0: m = dinv * (h0 @ W0) ---
    k_gemm_mma<false, false, true><<<NBLK, 256>>>(
        p_h, nullptr, DD, DD, 8, p_wt, DD, nullptr, nullptr,
        nullptr, nullptr, nullptr, nullptr, NN);
    k_agg_stats<<<NN / 8, 256>>>(b_gcn, p_stats);

    // --- layers 1..3: BN_{l-1}+relu+residual fused into A-load ---
    for (int l = 1; l < LL; l++) {
        k_gemm_mma<false, true, true><<<NBLK, 256>>>(
            p_h, p_h, DD, DD, 8, p_wt + l * DD * DD, DD, nullptr, nullptr,
            p_stats + (l - 1) * 2 * DD,
            bn_gamma + (l - 1) * DD, bn_beta + (l - 1) * DD,
            p_agg, NN);
        k_agg_stats<<<NN / 8, 256>>>(b_gcn + l * DD, p_stats + l * 2 * DD);
    }

    // --- fused BN3 + mean-pool + MLP ---
    k_pool_mlp<<<GG, 256>>>(bn_gamma + 3 * DD, bn_beta + 3 * DD,
                            W_r1, b_r1, W_r2, b_r2, W_r3, b_r3, out);
}

// round 11
// speedup vs baseline: 1.4593x; 1.0943x over previous
#include <cuda_runtime.h>
#include <cuda_fp16.h>
#include <math.h>
#include <cstdint>

#define NN   50000
#define EE   800000
#define DINF 146
#define DD   128
#define GG   64
#define LL   4
#define NCLS 10
#define ET   (EE + NN)
#define BNEPS 1e-5f

// ---------------- scratch (__device__ globals; no allocs allowed) -----------
__device__ float d_h[NN * DD];        // node features (running h)
__device__ uint2 d_mh[NN * 32];       // m_scaled = dinv*h@W, fp16 (128 halves/row)
__device__ float d_agg[NN * DD];      // aggregated messages (+bias), fp32
__device__ int   d_counts[NN];        // edge-only in-degree (zeroed in k_prep)
__device__ int   d_offs[NN + 1];
__device__ int   d_cursor[NN];
__device__ float d_dinv[NN];
__device__ int   d_ssrc[ET];
__device__ float d_stats[LL * 2 * DD];  // per-layer [sum | sumsq], zeroed in k_prep
__device__ int   d_gcnt[GG];
__device__ int   d_is64;
__device__ float d_wt[LL * DD * DD];  // transposed layer weights [l][n][k]
__device__ float d_wtp[DD * 160];     // transposed+padded emb weights [n][k<160]

// ---------------- index dtype handling --------------------------------------
__device__ __forceinline__ int ld_idx(const void* p, long long i, int is64) {
    return is64 ? (int)((const long long*)p)[i] : ((const int*)p)[i];
}

// ---------------- prep: dtype detect + weight transposes + zeroing -----------
__global__ void k_prep(const float* __restrict__ W_emb,
                       const float* __restrict__ W_gcn, const void* ei) {
    int idx = blockIdx.x * blockDim.x + threadIdx.x;
    if (idx == 0) {
        const long long* p = (const long long*)ei;
        int is64 = 1;
        for (int i = 0; i < 8; i++) {
            long long v = p[i];
            if (v < 0 || v >= NN) is64 = 0;
        }
        d_is64 = is64;
    }
    if (idx < NN) d_counts[idx] = 0;
    if (idx < GG) d_gcnt[idx] = 0;
    if (idx < LL * 2 * DD) d_stats[idx] = 0.f;
    if (idx < DD * 160) {
        int n = idx / 160, k = idx % 160;
        d_wtp[idx] = (k < DINF) ? W_emb[k * DD + n] : 0.f;
    } else if (idx < DD * 160 + LL * DD * DD) {
        int r2 = idx - DD * 160;
        int l = r2 / (DD * DD), r = r2 % (DD * DD);
        int n = r / DD, k = r % DD;
        d_wt[r2] = W_gcn[l * DD * DD + k * DD + n];
    }
}

// ---------------- hist: edge in-degree + batch histogram ---------------------
__global__ void k_hist(const void* ei, const void* batch) {
    int i = blockIdx.x * blockDim.x + threadIdx.x;
    int is64 = d_is64;
    if (i < EE) {
        atomicAdd(&d_counts[ld_idx(ei, (long long)EE + i, is64)], 1);
    } else if (i < EE + NN) {
        atomicAdd(&d_gcnt[ld_idx(batch, i - EE, is64)], 1);
    }
}

// ---------------- scan: offsets + dinv + cursor zero -------------------------
__global__ void k_scan() {
    __shared__ int s[1024];
    const int T = 1024;
    int t = threadIdx.x;
    const int chunk = (NN + T - 1) / T;
    int beg = t * chunk;
    int end = min(beg + chunk, NN);
    int sum = 0;
    for (int i = beg; i < end; i++) {
        int deg = d_counts[i] + 1;           // + self loop
        sum += deg;
        d_dinv[i] = rsqrtf((float)deg);
        d_cursor[i] = 0;
    }
    s[t] = sum;
    __syncthreads();
    for (int off = 1; off < T; off <<= 1) {
        int v = (t >= off) ? s[t - off] : 0;
        __syncthreads();
        s[t] += v;
        __syncthreads();
    }
    int run = (t == 0) ? 0 : s[t - 1];
    for (int i = beg; i < end; i++) { d_offs[i] = run; run += d_counts[i] + 1; }
    if (t == T - 1) d_offs[NN] = run;
}

__global__ void k_scatter(const void* ei) {
    long long e = (long long)blockIdx.x * blockDim.x + threadIdx.x;
    int is64 = d_is64;
    if (e < EE) {
        int s = ld_idx(ei, e, is64);
        int d = ld_idx(ei, (long long)EE + e, is64);
        int p = d_offs[d] + atomicAdd(&d_cursor[d], 1);
        d_ssrc[p] = s;
    } else if (e < ET) {
        int i = (int)(e - EE);
        int p = d_offs[i] + atomicAdd(&d_cursor[i], 1);
        d_ssrc[p] = i;
    }
}

// ======================= fp16 mma.sync GEMM (m16n8k16) ======================
// C[M,128] = A[M,K] @ Bt[128,K]^T.  CTA tile 128x128, BK=32 halves, 8 warps,
// double-buffered smem.  Rows stored as 16 half2 with 4x4 transpose on half2
// units: one LDS.128 at uint4-index qc yields pairs {qc,qc+4,qc+8,qc+12} =
// (a0,a2) for k16-step0 and k16-step1.  fp32 accumulate.
// FUSE_BN: A-load applies h_new = h + relu(agg*scale+shift), writes h back.
// HALF_OUT: epilogue writes dinv[row]*acc as fp16 into d_mh.

__device__ __forceinline__ uint32_t pack2(float a, float b) {
    __half2 h = __floats2half2_rn(a, b);
    return *reinterpret_cast<uint32_t*>(&h);
}

__device__ __forceinline__ void mma_f16(float* d, uint32_t a0, uint32_t a1,
                                        uint32_t a2, uint32_t a3,
                                        uint32_t b0, uint32_t b1) {
    asm volatile(
        "mma.sync.aligned.m16n8k16.row.col.f32.f16.f16.f32 "
        "{%0,%1,%2,%3}, {%4,%5,%6,%7}, {%8,%9}, {%0,%1,%2,%3};"
        : "+f"(d[0]), "+f"(d[1]), "+f"(d[2]), "+f"(d[3])
        : "r"(a0), "r"(a1), "r"(a2), "r"(a3), "r"(b0), "r"(b1));
}

template<bool PADK, bool FUSE_BN, bool HALF_OUT>
__global__ __launch_bounds__(256, 2) void k_gemm_mma(
    const float* __restrict__ A, float* __restrict__ Aw,
    int lda, int kmax, int kiters,
    const float* __restrict__ Bt, int ldb,
    const float* __restrict__ bias, float* __restrict__ Cf,
    const float* __restrict__ statsPrev,
    const float* __restrict__ gammaPrev, const float* __restrict__ betaPrev,
    const float* __restrict__ aggPrev, int M)
{
    __shared__ __align__(16) uint32_t As[2][128 * 16];
    __shared__ __align__(16) uint32_t Bs[2][128 * 16];
    __shared__ float s_sc[DD], s_sh[DD];

    int t = threadIdx.x;
    int wid = t >> 5, lane = t & 31;
    int wm = wid & 3, wn = wid >> 2;
    int qr = lane >> 2, qc = lane & 3;
    int m0 = blockIdx.x * 128;

    if (FUSE_BN) {
        if (t < DD) {
            float mu = statsPrev[t] * (1.f / NN);
            float var = statsPrev[DD + t] * (1.f / NN) - mu * mu;
            float sc = gammaPrev[t] * rsqrtf(var + BNEPS);
            s_sc[t] = sc;
            s_sh[t] = betaPrev[t] - mu * sc;
        }
        __syncthreads();
    }

    float acc[2][8][4];
#pragma unroll
    for (int mi = 0; mi < 2; mi++)
#pragma unroll
        for (int ni = 0; ni < 8; ni++)
#pragma unroll
            for (int j = 0; j < 4; j++) acc[mi][ni][j] = 0.f;

    uint32_t ra[2][4], rb[2][4];

    // stage one BK=32 tile into half2-packed registers
    auto load_tile = [&](int kk) {
#pragma unroll
        for (int i = 0; i < 2; i++) {
            int slot = t + i * 256;
            int r = slot >> 2, c = slot & 3;
            int grow = m0 + r;
            float f[8];
            if (PADK) {
#pragma unroll
                for (int d = 0; d < 8; d++) {
                    int k = kk + c * 8 + d;
                    f[d] = (grow < M && k < kmax)
                         ? A[(size_t)grow * lda + k] : 0.f;
                }
            } else {
                float4 v0 = make_float4(0.f, 0.f, 0.f, 0.f);
                float4 v1 = make_float4(0.f, 0.f, 0.f, 0.f);
                if (grow < M) {
                    size_t off = (size_t)grow * lda + kk + c * 8;
                    v0 = *reinterpret_cast<const float4*>(A + off);
                    v1 = *reinterpret_cast<const float4*>(A + off + 4);
                    if (FUSE_BN) {
                        float4 g0 = *reinterpret_cast<const float4*>(aggPrev + off);
                        float4 g1 = *reinterpret_cast<const float4*>(aggPrev + off + 4);
                        int col = kk + c * 8;
                        v0.x += fmaxf(0.f, g0.x * s_sc[col + 0] + s_sh[col + 0]);
                        v0.y += fmaxf(0.f, g0.y * s_sc[col + 1] + s_sh[col + 1]);
                        v0.z += fmaxf(0.f, g0.z * s_sc[col + 2] + s_sh[col + 2]);
                        v0.w += fmaxf(0.f, g0.w * s_sc[col + 3] + s_sh[col + 3]);
                        v1.x += fmaxf(0.f, g1.x * s_sc[col + 4] + s_sh[col + 4]);
                        v1.y += fmaxf(0.f, g1.y * s_sc[col + 5] + s_sh[col + 5]);
                        v1.z += fmaxf(0.f, g1.z * s_sc[col + 6] + s_sh[col + 6]);
                        v1.w += fmaxf(0.f, g1.w * s_sc[col + 7] + s_sh[col + 7]);
                        *reinterpret_cast<float4*>(Aw + off) = v0;
                        *reinterpret_cast<float4*>(Aw + off + 4) = v1;
                    }
                }
                f[0] = v0.x; f[1] = v0.y; f[2] = v0.z; f[3] = v0.w;
                f[4] = v1.x; f[5] = v1.y; f[6] = v1.z; f[7] = v1.w;
            }
            ra[i][0] = pack2(f[0], f[1]);
            ra[i][1] = pack2(f[2], f[3]);
            ra[i][2] = pack2(f[4], f[5]);
            ra[i][3] = pack2(f[6], f[7]);

            const float* br = Bt + (size_t)r * ldb + kk + c * 8;
            float4 w0 = *reinterpret_cast<const float4*>(br);
            float4 w1 = *reinterpret_cast<const float4*>(br + 4);
            rb[i][0] = pack2(w0.x, w0.y);
            rb[i][1] = pack2(w0.z, w0.w);
            rb[i][2] = pack2(w1.x, w1.y);
            rb[i][3] = pack2(w1.z, w1.w);
        }
    };

    load_tile(0);

    int buf = 0;
    for (int it = 0; it < kiters; it++) {
        // store staged tile: position d*4+c holds half2-pair index c*4+d
#pragma unroll
        for (int i = 0; i < 2; i++) {
            int slot = t + i * 256;
            int r = slot >> 2, c = slot & 3;
#pragma unroll
            for (int d = 0; d < 4; d++) {
                As[buf][r * 16 + d * 4 + c] = ra[i][d];
                Bs[buf][r * 16 + d * 4 + c] = rb[i][d];
            }
        }
        __syncthreads();

        if (it + 1 < kiters) load_tile((it + 1) * 32);

        const uint4* As4 = reinterpret_cast<const uint4*>(As[buf]);
        const uint4* Bs4 = reinterpret_cast<const uint4*>(Bs[buf]);

        uint4 af[2][2];
#pragma unroll
        for (int mi = 0; mi < 2; mi++)
#pragma unroll
            for (int h = 0; h < 2; h++) {
                int row = wm * 32 + mi * 16 + h * 8 + qr;
                af[mi][h] = As4[row * 4 + qc];
            }
#pragma unroll
        for (int ni = 0; ni < 8; ni++) {
            int row = wn * 64 + ni * 8 + qr;
            uint4 bf = Bs4[row * 4 + qc];
#pragma unroll
            for (int mi = 0; mi < 2; mi++) {
                // k16 step 0: a0,a1,a2,a3 = (.x row qr), (.x row qr+8), (.y qr), (.y qr+8)
                mma_f16(acc[mi][ni], af[mi][0].x, af[mi][1].x,
                        af[mi][0].y, af[mi][1].y, bf.x, bf.y);
                // k16 step 1
                mma_f16(acc[mi][ni], af[mi][0].z, af[mi][1].z,
                        af[mi][0].w, af[mi][1].w, bf.z, bf.w);
            }
        }
        __syncthreads();
        buf ^= 1;
    }

    // ---- epilogue ----
#pragma unroll
    for (int mi = 0; mi < 2; mi++) {
        int r0 = m0 + wm * 32 + mi * 16 + qr;
        int r1 = r0 + 8;
        if (HALF_OUT) {
            float dv0 = (r0 < M) ? d_dinv[r0] : 0.f;
            float dv1 = (r1 < M) ? d_dinv[r1] : 0.f;
            __half2* mh2 = reinterpret_cast<__half2*>(d_mh);
#pragma unroll
            for (int ni = 0; ni < 8; ni++) {
                int col = wn * 64 + ni * 8 + qc * 2;
                if (r0 < M)
                    mh2[(size_t)r0 * 64 + (col >> 1)] =
                        __floats2half2_rn(acc[mi][ni][0] * dv0, acc[mi][ni][1] * dv0);
                if (r1 < M)
                    mh2[(size_t)r1 * 64 + (col >> 1)] =
                        __floats2half2_rn(acc[mi][ni][2] * dv1, acc[mi][ni][3] * dv1);
            }
        } else {
#pragma unroll
            for (int ni = 0; ni < 8; ni++) {
                int col = wn * 64 + ni * 8 + qc * 2;
                float b0 = 0.f, b1 = 0.f;
                if (bias) { b0 = bias[col]; b1 = bias[col + 1]; }
                if (r0 < M) {
                    float2 o = make_float2(acc[mi][ni][0] + b0, acc[mi][ni][1] + b1);
                    *reinterpret_cast<float2*>(Cf + (size_t)r0 * DD + col) = o;
                }
                if (r1 < M) {
                    float2 o = make_float2(acc[mi][ni][2] + b0, acc[mi][ni][3] + b1);
                    *reinterpret_cast<float2*>(Cf + (size_t)r1 * DD + col) = o;
                }
            }
        }
    }
}

// ---------------- edge aggregation + BN stats --------------------------------
// warp per node: agg[n] = dinv[n] * sum_e m_scaled[src[e]] + bias.
// stats via two-phase smem reduction (no smem atomics).
__global__ __launch_bounds__(256) void k_agg_stats(
    const float* __restrict__ bias, float* __restrict__ stats)
{
    __shared__ float psum[8][DD], psq[8][DD];
    int t = threadIdx.x;
    int wid = t >> 5, lane = t & 31;
    int node = blockIdx.x * 8 + wid;     // NN = 50000 = 6250*8, always valid

    int e0 = d_offs[node], e1 = d_offs[node + 1];
    float a0 = 0.f, a1 = 0.f, a2 = 0.f, a3 = 0.f;
    int e = e0;
    for (; e + 4 <= e1; e += 4) {
        int s0 = d_ssrc[e],     s1 = d_ssrc[e + 1];
        int s2 = d_ssrc[e + 2], s3 = d_ssrc[e + 3];
        uint2 v0 = d_mh[(size_t)s0 * 32 + lane];
        uint2 v1 = d_mh[(size_t)s1 * 32 + lane];
        uint2 v2 = d_mh[(size_t)s2 * 32 + lane];
        uint2 v3 = d_mh[(size_t)s3 * 32 + lane];
        float2 f00 = __half22float2(*reinterpret_cast<__half2*>(&v0.x));
        float2 f01 = __half22float2(*reinterpret_cast<__half2*>(&v0.y));
        float2 f10 = __half22float2(*reinterpret_cast<__half2*>(&v1.x));
        float2 f11 = __half22float2(*reinterpret_cast<__half2*>(&v1.y));
        float2 f20 = __half22float2(*reinterpret_cast<__half2*>(&v2.x));
        float2 f21 = __half22float2(*reinterpret_cast<__half2*>(&v2.y));
        float2 f30 = __half22float2(*reinterpret_cast<__half2*>(&v3.x));
        float2 f31 = __half22float2(*reinterpret_cast<__half2*>(&v3.y));
        a0 += (f00.x + f10.x) + (f20.x + f30.x);
        a1 += (f00.y + f10.y) + (f20.y + f30.y);
        a2 += (f01.x + f11.x) + (f21.x + f31.x);
        a3 += (f01.y + f11.y) + (f21.y + f31.y);
    }
    for (; e < e1; e++) {
        int s0 = d_ssrc[e];
        uint2 v0 = d_mh[(size_t)s0 * 32 + lane];
        float2 f00 = __half22float2(*reinterpret_cast<__half2*>(&v0.x));
        float2 f01 = __half22float2(*reinterpret_cast<__half2*>(&v0.y));
        a0 += f00.x; a1 += f00.y; a2 += f01.x; a3 += f01.y;
    }
    float dv = d_dinv[node];
    float4 b = reinterpret_cast<const float4*>(bias)[lane];
    a0 = a0 * dv + b.x;
    a1 = a1 * dv + b.y;
    a2 = a2 * dv + b.z;
    a3 = a3 * dv + b.w;
    reinterpret_cast<float4*>(d_agg)[(size_t)node * 32 + lane] =
        make_float4(a0, a1, a2, a3);

    reinterpret_cast<float4*>(&psum[wid][0])[lane] = make_float4(a0, a1, a2, a3);
    reinterpret_cast<float4*>(&psq[wid][0])[lane] =
        make_float4(a0 * a0, a1 * a1, a2 * a2, a3 * a3);
    __syncthreads();

    if (t < DD) {
        float s = psum[0][t] + psum[1][t] + psum[2][t] + psum[3][t]
                + psum[4][t] + psum[5][t] + psum[6][t] + psum[7][t];
        atomicAdd(&stats[t], s);
    } else {
        int c = t - DD;
        float q = psq[0][c] + psq[1][c] + psq[2][c] + psq[3][c]
                + psq[4][c] + psq[5][c] + psq[6][c] + psq[7][c];
        atomicAdd(&stats[DD + c], q);
    }
}

// ---------------- fused BN3 + mean-pool + MLP readout -------------------------
__global__ __launch_bounds__(256) void k_pool_mlp(
    const float* __restrict__ gamma, const float* __restrict__ beta,
    const float* __restrict__ W1, const float* __restrict__ b1,
    const float* __restrict__ W2, const float* __restrict__ b2,
    const float* __restrict__ W3, const float* __restrict__ b3,
    float* __restrict__ out)
{
    __shared__ float sc[DD], sh[DD], hg[DD], z1[64], z2[32], part[2][DD];
    __shared__ int sst;
    int g = blockIdx.x, t = threadIdx.x;
    int tt = t & 127, half = t >> 7;

    if (t < DD) {
        const float* st = d_stats + 3 * 2 * DD;
        float mu = st[t] * (1.f / NN);
        float var = st[DD + t] * (1.f / NN) - mu * mu;
        float s = gamma[t] * rsqrtf(var + BNEPS);
        sc[t] = s;
        sh[t] = beta[t] - mu * s;
    }
    if (t == 0) {
        int run = 0;
        for (int i = 0; i < g; i++) run += d_gcnt[i];
        sst = run;
    }
    __syncthreads();

    int s0 = sst, c = d_gcnt[g];
    float acc = 0.f;
    for (int r = half; r < c; r += 2) {
        size_t off = (size_t)(s0 + r) * DD + tt;
        acc += d_h[off] + fmaxf(0.f, d_agg[off] * sc[tt] + sh[tt]);
    }
    part[half][tt] = acc;
    __syncthreads();
    if (t < DD) hg[t] = (part[0][t] + part[1][t]) / fmaxf((float)c, 1.f);
    __syncthreads();

    if (t < 64) {
        float a = b1[t];
        for (int k = 0; k < DD; k++) a = fmaf(hg[k], W1[k * 64 + t], a);
        z1[t] = fmaxf(0.f, a);
    }
    __syncthreads();
    if (t < 32) {
        float a = b2[t];
        for (int k = 0; k < 64; k++) a = fmaf(z1[k], W2[k * 32 + t], a);
        z2[t] = fmaxf(0.f, a);
    }
    __syncthreads();
    if (t < NCLS) {
        float a = b3[t];
        for (int k = 0; k < 32; k++) a = fmaf(z2[k], W3[k * NCLS + t], a);
        out[g * NCLS + t] = a;
    }
}

// ---------------- launch ------------------------------------------------------
extern "C" void kernel_launch(void* const* d_in, const int* in_sizes, int n_in,
                              void* d_out, int out_size) {
    const float* x        = (const float*)d_in[0];
    const void*  ei       = d_in[1];
    const void*  batch    = d_in[2];
    const float* W_emb    = (const float*)d_in[3];
    const float* b_emb    = (const float*)d_in[4];
    const float* W_gcn    = (const float*)d_in[5];
    const float* b_gcn    = (const float*)d_in[6];
    const float* bn_gamma = (const float*)d_in[7];
    const float* bn_beta  = (const float*)d_in[8];
    const float* W_r1     = (const float*)d_in[9];
    const float* b_r1     = (const float*)d_in[10];
    const float* W_r2     = (const float*)d_in[11];
    const float* b_r2     = (const float*)d_in[12];
    const float* W_r3     = (const float*)d_in[13];
    const float* b_r3     = (const float*)d_in[14];
    float* out = (float*)d_out;

    float* p_h;      cudaGetSymbolAddress((void**)&p_h, d_h);
    float* p_agg;    cudaGetSymbolAddress((void**)&p_agg, d_agg);
    float* p_wt;     cudaGetSymbolAddress((void**)&p_wt, d_wt);
    float* p_wtp;    cudaGetSymbolAddress((void**)&p_wtp, d_wtp);
    float* p_stats;  cudaGetSymbolAddress((void**)&p_stats, d_stats);

    const int NBLK = (NN + 127) / 128;   // 391
    const int PREP = DD * 160 + LL * DD * DD;

    // --- preprocessing (also zeroes counts / gcnt / stats) ---
    k_prep<<<(PREP + 255) / 256, 256>>>(W_emb, W_gcn, ei);
    k_hist<<<(EE + NN + 255) / 256, 256>>>(ei, batch);
    k_scan<<<1, 1024>>>();
    k_scatter<<<(ET + 255) / 256, 256>>>(ei);

    // --- embedding: h0 = x @ W_emb + b_emb  (K=146 padded to 160, 5 BK=32 iters)
    k_gemm_mma<true, false, false><<<NBLK, 256>>>(
        x, nullptr, DINF, DINF, 5, p_wtp, 160, b_emb, p_h,
        nullptr, nullptr, nullptr, nullptr, NN);

    // --- layer 0: m = dinv * (h0 @ W0) ---
    k_gemm_mma<false, false, true><<<NBLK, 256>>>(
        p_h, nullptr, DD, DD, 4, p_wt, DD, nullptr, nullptr,
        nullptr, nullptr, nullptr, nullptr, NN);
    k_agg_stats<<<NN / 8, 256>>>(b_gcn, p_stats);

    // --- layers 1..3: BN_{l-1}+relu+residual fused into A-load ---
    for (int l = 1; l < LL; l++) {
        k_gemm_mma<false, true, true><<<NBLK, 256>>>(
            p_h, p_h, DD, DD, 4, p_wt + l * DD * DD, DD, nullptr, nullptr,
            p_stats + (l - 1) * 2 * DD,
            bn_gamma + (l - 1) * DD, bn_beta + (l - 1) * DD,
            p_agg, NN);
        k_agg_stats<<<NN / 8, 256>>>(b_gcn + l * DD, p_stats + l * 2 * DD);
    }

    // --- fused BN3 + mean-pool + MLP ---
    k_pool_mlp<<<GG, 256>>>(bn_gamma + 3 * DD, bn_beta + 3 * DD,
                            W_r1, b_r1, W_r2, b_r2, W_r3, b_r3, out);
}

// round 12
// speedup vs baseline: 1.5053x; 1.0316x over previous
#include <cuda_runtime.h>
#include <cuda_fp16.h>
#include <math.h>
#include <cstdint>

#define NN   50000
#define EE   800000
#define DINF 146
#define DD   128
#define GG   64
#define LL   4
#define NCLS 10
#define ET   (EE + NN)
#define BNEPS 1e-5f

// ---------------- scratch (__device__ globals; no allocs allowed) -----------
__device__ float  d_h[NN * DD];        // node features (running h)
__device__ uint2  d_mh[NN * 32];       // m_scaled = dinv*h@W, fp16
__device__ float  d_agg[NN * DD];      // aggregated messages (+bias), fp32
__device__ int    d_counts[NN];
__device__ int    d_offs[NN + 1];
__device__ int    d_cursor[NN];
__device__ float  d_dinv[NN];
__device__ int    d_ssrc[ET];
__device__ float  d_stats[LL * 2 * DD];  // per-layer [sum | sumsq], zeroed in k_prep
__device__ int    d_gcnt[GG];
__device__ int    d_is64;
__device__ __half d_wth[LL * DD * DD]; // fp16 transposed layer weights [l][n][k]
__device__ __half d_wtph[DD * 160];    // fp16 transposed+padded emb weights

// ---------------- index dtype handling --------------------------------------
__device__ __forceinline__ int ld_idx(const void* p, long long i, int is64) {
    return is64 ? (int)((const long long*)p)[i] : ((const int*)p)[i];
}

// ---------------- prep: dtype detect + weight transpose/convert + zeroing ----
__global__ void k_prep(const float* __restrict__ W_emb,
                       const float* __restrict__ W_gcn, const void* ei) {
    int idx = blockIdx.x * blockDim.x + threadIdx.x;
    if (idx == 0) {
        const long long* p = (const long long*)ei;
        int is64 = 1;
        for (int i = 0; i < 8; i++) {
            long long v = p[i];
            if (v < 0 || v >= NN) is64 = 0;
        }
        d_is64 = is64;
    }
    if (idx < NN) d_counts[idx] = 0;
    if (idx < GG) d_gcnt[idx] = 0;
    if (idx < LL * 2 * DD) d_stats[idx] = 0.f;
    if (idx < DD * 160) {
        int n = idx / 160, k = idx % 160;
        d_wtph[idx] = __float2half((k < DINF) ? W_emb[k * DD + n] : 0.f);
    } else if (idx < DD * 160 + LL * DD * DD) {
        int r2 = idx - DD * 160;
        int l = r2 / (DD * DD), r = r2 % (DD * DD);
        int n = r / DD, k = r % DD;
        d_wth[r2] = __float2half(W_gcn[l * DD * DD + k * DD + n]);
    }
}

// ---------------- hist: edge in-degree + batch histogram ---------------------
__global__ void k_hist(const void* ei, const void* batch) {
    int i = blockIdx.x * blockDim.x + threadIdx.x;
    int is64 = d_is64;
    if (i < EE) {
        atomicAdd(&d_counts[ld_idx(ei, (long long)EE + i, is64)], 1);
    } else if (i < EE + NN) {
        atomicAdd(&d_gcnt[ld_idx(batch, i - EE, is64)], 1);
    }
}

// ---------------- scan: offsets + dinv + cursor zero -------------------------
__global__ void k_scan() {
    __shared__ int s[1024];
    const int T = 1024;
    int t = threadIdx.x;
    const int chunk = (NN + T - 1) / T;
    int beg = t * chunk;
    int end = min(beg + chunk, NN);
    int sum = 0;
    for (int i = beg; i < end; i++) {
        int deg = d_counts[i] + 1;           // + self loop
        sum += deg;
        d_dinv[i] = rsqrtf((float)deg);
        d_cursor[i] = 0;
    }
    s[t] = sum;
    __syncthreads();
    for (int off = 1; off < T; off <<= 1) {
        int v = (t >= off) ? s[t - off] : 0;
        __syncthreads();
        s[t] += v;
        __syncthreads();
    }
    int run = (t == 0) ? 0 : s[t - 1];
    for (int i = beg; i < end; i++) { d_offs[i] = run; run += d_counts[i] + 1; }
    if (t == T - 1) d_offs[NN] = run;
}

__global__ void k_scatter(const void* ei) {
    long long e = (long long)blockIdx.x * blockDim.x + threadIdx.x;
    int is64 = d_is64;
    if (e < EE) {
        int s = ld_idx(ei, e, is64);
        int d = ld_idx(ei, (long long)EE + e, is64);
        int p = d_offs[d] + atomicAdd(&d_cursor[d], 1);
        d_ssrc[p] = s;
    } else if (e < ET) {
        int i = (int)(e - EE);
        int p = d_offs[i] + atomicAdd(&d_cursor[i], 1);
        d_ssrc[p] = i;
    }
}

// ================= fp16 mma.sync GEMM (m16n8k16), SINGLE STAGE ==============
// C[M,128] = A[M,K] @ Bt[128,K]^T.  CTA tile 128x128, FULL K resident in
// dynamic smem (KC chunks of 32 halves), ONE barrier, then 128 HMMA/warp.
// Per-chunk layout: [128 rows x 16 uint32], rows 4x4-transposed on half2 so
// one LDS.128 at uint4-idx qc yields pairs {qc,qc+4,qc+8,qc+12}.
// FUSE_BN: A-load applies h_new = h + relu(agg*scale+shift), writes h back.
// HALF_OUT: epilogue writes dinv[row]*acc as fp16 into d_mh.

__device__ __forceinline__ uint32_t pack2(float a, float b) {
    __half2 h = __floats2half2_rn(a, b);
    return *reinterpret_cast<uint32_t*>(&h);
}

__device__ __forceinline__ void mma_f16(float* d, uint32_t a0, uint32_t a1,
                                        uint32_t a2, uint32_t a3,
                                        uint32_t b0, uint32_t b1) {
    asm volatile(
        "mma.sync.aligned.m16n8k16.row.col.f32.f16.f16.f32 "
        "{%0,%1,%2,%3}, {%4,%5,%6,%7}, {%8,%9}, {%0,%1,%2,%3};"
        : "+f"(d[0]), "+f"(d[1]), "+f"(d[2]), "+f"(d[3])
        : "r"(a0), "r"(a1), "r"(a2), "r"(a3), "r"(b0), "r"(b1));
}

template<int KC, bool PADK, bool FUSE_BN, bool HALF_OUT>
__global__ __launch_bounds__(256, 2) void k_gemm_mma(
    const float* __restrict__ A, float* __restrict__ Aw,
    int lda, int kmax,
    const __half* __restrict__ Bth, int ldbh,
    const float* __restrict__ bias, float* __restrict__ Cf,
    const float* __restrict__ statsPrev,
    const float* __restrict__ gammaPrev, const float* __restrict__ betaPrev,
    const float* __restrict__ aggPrev, int M)
{
    extern __shared__ __align__(16) uint32_t smdyn[];
    uint32_t* As = smdyn;                 // KC * 2048 uint32
    uint32_t* Bs = smdyn + KC * 2048;     // KC * 2048 uint32
    __shared__ float s_sc[DD], s_sh[DD];

    int t = threadIdx.x;
    int wid = t >> 5, lane = t & 31;
    int wm = wid & 3, wn = wid >> 2;
    int qr = lane >> 2, qc = lane & 3;
    int m0 = blockIdx.x * 128;

    if (FUSE_BN) {
        if (t < DD) {
            float mu = statsPrev[t] * (1.f / NN);
            float var = statsPrev[DD + t] * (1.f / NN) - mu * mu;
            float sc = gammaPrev[t] * rsqrtf(var + BNEPS);
            s_sc[t] = sc;
            s_sh[t] = betaPrev[t] - mu * sc;
        }
        __syncthreads();
    }

    // ---- single load stage: all KC chunks of A and B ----
#pragma unroll
    for (int s = 0; s < KC * 2; s++) {
        int slot = t + s * 256;
        int r = slot / (KC * 4);
        int cc = slot - r * (KC * 4);
        int chunk = cc >> 2, c = cc & 3;
        int grow = m0 + r;

        uint32_t pa0, pa1, pa2, pa3;
        if (PADK) {
            float f[8];
#pragma unroll
            for (int d = 0; d < 8; d++) {
                int k = cc * 8 + d;
                f[d] = (grow < M && k < kmax) ? A[(size_t)grow * lda + k] : 0.f;
            }
            pa0 = pack2(f[0], f[1]); pa1 = pack2(f[2], f[3]);
            pa2 = pack2(f[4], f[5]); pa3 = pack2(f[6], f[7]);
        } else {
            float4 v0 = make_float4(0.f, 0.f, 0.f, 0.f);
            float4 v1 = make_float4(0.f, 0.f, 0.f, 0.f);
            if (grow < M) {
                size_t off = (size_t)grow * lda + cc * 8;
                v0 = *reinterpret_cast<const float4*>(A + off);
                v1 = *reinterpret_cast<const float4*>(A + off + 4);
                if (FUSE_BN) {
                    float4 g0 = *reinterpret_cast<const float4*>(aggPrev + off);
                    float4 g1 = *reinterpret_cast<const float4*>(aggPrev + off + 4);
                    int col = cc * 8;
                    v0.x += fmaxf(0.f, g0.x * s_sc[col + 0] + s_sh[col + 0]);
                    v0.y += fmaxf(0.f, g0.y * s_sc[col + 1] + s_sh[col + 1]);
                    v0.z += fmaxf(0.f, g0.z * s_sc[col + 2] + s_sh[col + 2]);
                    v0.w += fmaxf(0.f, g0.w * s_sc[col + 3] + s_sh[col + 3]);
                    v1.x += fmaxf(0.f, g1.x * s_sc[col + 4] + s_sh[col + 4]);
                    v1.y += fmaxf(0.f, g1.y * s_sc[col + 5] + s_sh[col + 5]);
                    v1.z += fmaxf(0.f, g1.z * s_sc[col + 6] + s_sh[col + 6]);
                    v1.w += fmaxf(0.f, g1.w * s_sc[col + 7] + s_sh[col + 7]);
                    *reinterpret_cast<float4*>(Aw + off) = v0;
                    *reinterpret_cast<float4*>(Aw + off + 4) = v1;
                }
            }
            pa0 = pack2(v0.x, v0.y); pa1 = pack2(v0.z, v0.w);
            pa2 = pack2(v1.x, v1.y); pa3 = pack2(v1.z, v1.w);
        }
        uint32_t* dstA = &As[chunk * 2048 + r * 16 + c];
        dstA[0] = pa0; dstA[4] = pa1; dstA[8] = pa2; dstA[12] = pa3;

        uint4 wb = *reinterpret_cast<const uint4*>(Bth + (size_t)r * ldbh + cc * 8);
        uint32_t* dstB = &Bs[chunk * 2048 + r * 16 + c];
        dstB[0] = wb.x; dstB[4] = wb.y; dstB[8] = wb.z; dstB[12] = wb.w;
    }
    __syncthreads();

    // ---- compute: KC chunks, no further barriers ----
    float acc[2][8][4];
#pragma unroll
    for (int mi = 0; mi < 2; mi++)
#pragma unroll
        for (int ni = 0; ni < 8; ni++)
#pragma unroll
            for (int j = 0; j < 4; j++) acc[mi][ni][j] = 0.f;

    const uint4* As4 = reinterpret_cast<const uint4*>(As);
    const uint4* Bs4 = reinterpret_cast<const uint4*>(Bs);
#pragma unroll
    for (int chunk = 0; chunk < KC; chunk++) {
        const uint4* Ac = As4 + chunk * 512;
        const uint4* Bc = Bs4 + chunk * 512;
        uint4 af[2][2];
#pragma unroll
        for (int mi = 0; mi < 2; mi++)
#pragma unroll
            for (int h = 0; h < 2; h++) {
                int row = wm * 32 + mi * 16 + h * 8 + qr;
                af[mi][h] = Ac[row * 4 + qc];
            }
#pragma unroll
        for (int ni = 0; ni < 8; ni++) {
            int row = wn * 64 + ni * 8 + qr;
            uint4 bf = Bc[row * 4 + qc];
#pragma unroll
            for (int mi = 0; mi < 2; mi++) {
                mma_f16(acc[mi][ni], af[mi][0].x, af[mi][1].x,
                        af[mi][0].y, af[mi][1].y, bf.x, bf.y);
                mma_f16(acc[mi][ni], af[mi][0].z, af[mi][1].z,
                        af[mi][0].w, af[mi][1].w, bf.z, bf.w);
            }
        }
    }

    // ---- epilogue ----
#pragma unroll
    for (int mi = 0; mi < 2; mi++) {
        int r0 = m0 + wm * 32 + mi * 16 + qr;
        int r1 = r0 + 8;
        if (HALF_OUT) {
            float dv0 = (r0 < M) ? d_dinv[r0] : 0.f;
            float dv1 = (r1 < M) ? d_dinv[r1] : 0.f;
            __half2* mh2 = reinterpret_cast<__half2*>(d_mh);
#pragma unroll
            for (int ni = 0; ni < 8; ni++) {
                int col = wn * 64 + ni * 8 + qc * 2;
                if (r0 < M)
                    mh2[(size_t)r0 * 64 + (col >> 1)] =
                        __floats2half2_rn(acc[mi][ni][0] * dv0, acc[mi][ni][1] * dv0);
                if (r1 < M)
                    mh2[(size_t)r1 * 64 + (col >> 1)] =
                        __floats2half2_rn(acc[mi][ni][2] * dv1, acc[mi][ni][3] * dv1);
            }
        } else {
#pragma unroll
            for (int ni = 0; ni < 8; ni++) {
                int col = wn * 64 + ni * 8 + qc * 2;
                float b0 = 0.f, b1 = 0.f;
                if (bias) { b0 = bias[col]; b1 = bias[col + 1]; }
                if (r0 < M) {
                    float2 o = make_float2(acc[mi][ni][0] + b0, acc[mi][ni][1] + b1);
                    *reinterpret_cast<float2*>(Cf + (size_t)r0 * DD + col) = o;
                }
                if (r1 < M) {
                    float2 o = make_float2(acc[mi][ni][2] + b0, acc[mi][ni][3] + b1);
                    *reinterpret_cast<float2*>(Cf + (size_t)r1 * DD + col) = o;
                }
            }
        }
    }
}

// ---------------- edge aggregation + BN stats --------------------------------
__global__ __launch_bounds__(256) void k_agg_stats(
    const float* __restrict__ bias, float* __restrict__ stats)
{
    __shared__ float psum[8][DD], psq[8][DD];
    int t = threadIdx.x;
    int wid = t >> 5, lane = t & 31;
    int node = blockIdx.x * 8 + wid;     // NN = 50000 = 6250*8

    int e0 = d_offs[node], e1 = d_offs[node + 1];
    float a0 = 0.f, a1 = 0.f, a2 = 0.f, a3 = 0.f;
    int e = e0;
    for (; e + 4 <= e1; e += 4) {
        int s0 = d_ssrc[e],     s1 = d_ssrc[e + 1];
        int s2 = d_ssrc[e + 2], s3 = d_ssrc[e + 3];
        uint2 v0 = d_mh[(size_t)s0 * 32 + lane];
        uint2 v1 = d_mh[(size_t)s1 * 32 + lane];
        uint2 v2 = d_mh[(size_t)s2 * 32 + lane];
        uint2 v3 = d_mh[(size_t)s3 * 32 + lane];
        float2 f00 = __half22float2(*reinterpret_cast<__half2*>(&v0.x));
        float2 f01 = __half22float2(*reinterpret_cast<__half2*>(&v0.y));
        float2 f10 = __half22float2(*reinterpret_cast<__half2*>(&v1.x));
        float2 f11 = __half22float2(*reinterpret_cast<__half2*>(&v1.y));
        float2 f20 = __half22float2(*reinterpret_cast<__half2*>(&v2.x));
        float2 f21 = __half22float2(*reinterpret_cast<__half2*>(&v2.y));
        float2 f30 = __half22float2(*reinterpret_cast<__half2*>(&v3.x));
        float2 f31 = __half22float2(*reinterpret_cast<__half2*>(&v3.y));
        a0 += (f00.x + f10.x) + (f20.x + f30.x);
        a1 += (f00.y + f10.y) + (f20.y + f30.y);
        a2 += (f01.x + f11.x) + (f21.x + f31.x);
        a3 += (f01.y + f11.y) + (f21.y + f31.y);
    }
    for (; e < e1; e++) {
        int s0 = d_ssrc[e];
        uint2 v0 = d_mh[(size_t)s0 * 32 + lane];
        float2 f00 = __half22float2(*reinterpret_cast<__half2*>(&v0.x));
        float2 f01 = __half22float2(*reinterpret_cast<__half2*>(&v0.y));
        a0 += f00.x; a1 += f00.y; a2 += f01.x; a3 += f01.y;
    }
    float dv = d_dinv[node];
    float4 b = reinterpret_cast<const float4*>(bias)[lane];
    a0 = a0 * dv + b.x;
    a1 = a1 * dv + b.y;
    a2 = a2 * dv + b.z;
    a3 = a3 * dv + b.w;
    reinterpret_cast<float4*>(d_agg)[(size_t)node * 32 + lane] =
        make_float4(a0, a1, a2, a3);

    reinterpret_cast<float4*>(&psum[wid][0])[lane] = make_float4(a0, a1, a2, a3);
    reinterpret_cast<float4*>(&psq[wid][0])[lane] =
        make_float4(a0 * a0, a1 * a1, a2 * a2, a3 * a3);
    __syncthreads();

    if (t < DD) {
        float s = psum[0][t] + psum[1][t] + psum[2][t] + psum[3][t]
                + psum[4][t] + psum[5][t] + psum[6][t] + psum[7][t];
        atomicAdd(&stats[t], s);
    } else {
        int c = t - DD;
        float q = psq[0][c] + psq[1][c] + psq[2][c] + psq[3][c]
                + psq[4][c] + psq[5][c] + psq[6][c] + psq[7][c];
        atomicAdd(&stats[DD + c], q);
    }
}

// ---------------- fused BN3 + mean-pool + MLP readout -------------------------
__global__ __launch_bounds__(256) void k_pool_mlp(
    const float* __restrict__ gamma, const float* __restrict__ beta,
    const float* __restrict__ W1, const float* __restrict__ b1,
    const float* __restrict__ W2, const float* __restrict__ b2,
    const float* __restrict__ W3, const float* __restrict__ b3,
    float* __restrict__ out)
{
    __shared__ float sc[DD], sh[DD], hg[DD], z1[64], z2[32], part[2][DD];
    __shared__ int sst;
    int g = blockIdx.x, t = threadIdx.x;
    int tt = t & 127, half = t >> 7;

    if (t < DD) {
        const float* st = d_stats + 3 * 2 * DD;
        float mu = st[t] * (1.f / NN);
        float var = st[DD + t] * (1.f / NN) - mu * mu;
        float s = gamma[t] * rsqrtf(var + BNEPS);
        sc[t] = s;
        sh[t] = beta[t] - mu * s;
    }
    if (t == 0) {
        int run = 0;
        for (int i = 0; i < g; i++) run += d_gcnt[i];
        sst = run;
    }
    __syncthreads();

    int s0 = sst, c = d_gcnt[g];
    float acc = 0.f;
    for (int r = half; r < c; r += 2) {
        size_t off = (size_t)(s0 + r) * DD + tt;
        acc += d_h[off] + fmaxf(0.f, d_agg[off] * sc[tt] + sh[tt]);
    }
    part[half][tt] = acc;
    __syncthreads();
    if (t < DD) hg[t] = (part[0][t] + part[1][t]) / fmaxf((float)c, 1.f);
    __syncthreads();

    if (t < 64) {
        float a = b1[t];
        for (int k = 0; k < DD; k++) a = fmaf(hg[k], W1[k * 64 + t], a);
        z1[t] = fmaxf(0.f, a);
    }
    __syncthreads();
    if (t < 32) {
        float a = b2[t];
        for (int k = 0; k < 64; k++) a = fmaf(z1[k], W2[k * 32 + t], a);
        z2[t] = fmaxf(0.f, a);
    }
    __syncthreads();
    if (t < NCLS) {
        float a = b3[t];
        for (int k = 0; k < 32; k++) a = fmaf(z2[k], W3[k * NCLS + t], a);
        out[g * NCLS + t] = a;
    }
}

// ---------------- launch ------------------------------------------------------
extern "C" void kernel_launch(void* const* d_in, const int* in_sizes, int n_in,
                              void* d_out, int out_size) {
    const float* x        = (const float*)d_in[0];
    const void*  ei       = d_in[1];
    const void*  batch    = d_in[2];
    const float* W_emb    = (const float*)d_in[3];
    const float* b_emb    = (const float*)d_in[4];
    const float* W_gcn    = (const float*)d_in[5];
    const float* b_gcn    = (const float*)d_in[6];
    const float* bn_gamma = (const float*)d_in[7];
    const float* bn_beta  = (const float*)d_in[8];
    const float* W_r1     = (const float*)d_in[9];
    const float* b_r1     = (const float*)d_in[10];
    const float* W_r2     = (const float*)d_in[11];
    const float* b_r2     = (const float*)d_in[12];
    const float* W_r3     = (const float*)d_in[13];
    const float* b_r3     = (const float*)d_in[14];
    float* out = (float*)d_out;

    float*  p_h;     cudaGetSymbolAddress((void**)&p_h, d_h);
    float*  p_agg;   cudaGetSymbolAddress((void**)&p_agg, d_agg);
    float*  p_stats; cudaGetSymbolAddress((void**)&p_stats, d_stats);
    __half* p_wth;   cudaGetSymbolAddress((void**)&p_wth, d_wth);
    __half* p_wtph;  cudaGetSymbolAddress((void**)&p_wtph, d_wtph);

    const int NBLK = (NN + 127) / 128;   // 391
    const int PREP = DD * 160 + LL * DD * DD;
    const int SM4 = 4 * 2 * 2048 * 4;    // 65536 B
    const int SM5 = 5 * 2 * 2048 * 4;    // 81920 B

    static bool attr_done = false;
    if (!attr_done) {
        cudaFuncSetAttribute(k_gemm_mma<5, true, false, false>,
                             cudaFuncAttributeMaxDynamicSharedMemorySize, SM5);
        cudaFuncSetAttribute(k_gemm_mma<4, false, false, true>,
                             cudaFuncAttributeMaxDynamicSharedMemorySize, SM4);
        cudaFuncSetAttribute(k_gemm_mma<4, false, true, true>,
                             cudaFuncAttributeMaxDynamicSharedMemorySize, SM4);
        attr_done = true;
    }

    // --- preprocessing (also zeroes counts / gcnt / stats) ---
    k_prep<<<(PREP + 255) / 256, 256>>>(W_emb, W_gcn, ei);
    k_hist<<<(EE + NN + 255) / 256, 256>>>(ei, batch);
    k_scan<<<1, 1024>>>();
    k_scatter<<<(ET + 255) / 256, 256>>>(ei);

    // --- embedding: h0 = x @ W_emb + b_emb  (K=146 padded to 160, KC=5) ---
    k_gemm_mma<5, true, false, false><<<NBLK, 256, SM5>>>(
        x, nullptr, DINF, DINF, p_wtph, 160, b_emb, p_h,
        nullptr, nullptr, nullptr, nullptr, NN);

    // --- layer 0: m = dinv * (h0 @ W0) ---
    k_gemm_mma<4, false, false, true><<<NBLK, 256, SM4>>>(
        p_h, nullptr, DD, DD, p_wth, DD, nullptr, nullptr,
        nullptr, nullptr, nullptr, nullptr, NN);
    k_agg_stats<<<NN / 8, 256>>>(b_gcn, p_stats);

    // --- layers 1..3: BN_{l-1}+relu+residual fused into A-load ---
    for (int l = 1; l < LL; l++) {
        k_gemm_mma<4, false, true, true><<<NBLK, 256, SM4>>>(
            p_h, p_h, DD, DD, p_wth + l * DD * DD, DD, nullptr, nullptr,
            p_stats + (l - 1) * 2 * DD,
            bn_gamma + (l - 1) * DD, bn_beta + (l - 1) * DD,
            p_agg, NN);
        k_agg_stats<<<NN / 8, 256>>>(b_gcn + l * DD, p_stats + l * 2 * DD);
    }

    // --- fused BN3 + mean-pool + MLP ---
    k_pool_mlp<<<GG, 256>>>(bn_gamma + 3 * DD, bn_beta + 3 * DD,
                            W_r1, b_r1, W_r2, b_r2, W_r3, b_r3, out);
}